// round 12
// baseline (speedup 1.0000x reference)
#include <cuda_runtime.h>
#include <cuda_bf16.h>

#define NATOMS 768
#define H 100
#define IN_NODE 32
#define IN_EDGE 16
#define ITERS 3
#define NE (NATOMS * NATOMS)       // 589824

#define BM 128
#define NTILES (NE / BM)            // 4608
#define SEGS 6
#define KC 7                        // k16 steps covering 0..111
#define RS 58                       // row stride in u32 words (116 bf16)
#define ETHREADS 512

// smem word offsets for k_edge
#define OFF_WC 0                    // Wc hi/lo: 2 * 6032
#define OFF_WD 12064                // Wde hi/lo: 2 * 6032
#define OFF_FH 24128                // Fsum hi: 7424
#define OFF_FL 31552                // Fsum lo: 7424
#define OFF_RED 38976               // 8*104 f32
#define OFF_WZ 39808                // 1700 f32
#define OFF_WE2 41508               // 1700 f32
#define OFF_BZ 43208                // 100
#define OFF_BDE 43308               // 100
#define OFF_BE 43408                // 100
#define SMEM_WORDS 43508            // 174 KB

// ---- scratch (device globals; no allocation allowed) ----
__device__ float g_dots[NE];
__device__ float g_fi[NATOMS * H];
__device__ float g_fj[NATOMS * H];
__device__ float g_PS[SEGS * NATOMS * H];
__device__ float g_FSrow[NATOMS * H];
__device__ float g_SEa[NATOMS * IN_EDGE];
__device__ float g_Wc[H * H];              // W_de @ W_eij (fp32)
__device__ float g_Wz[H * 17];             // (W_edge@W_eij)^T padded: [c*17+k]
__device__ float g_We[H * 17];             // W_edge^T padded: [c*17+k]
__device__ float g_bz0[H];                 // b_edge@W_eij + b_eij
__device__ float g_bde[H];                 // b_de@W_eij
// 3-term split weights, n-major 104 x 116 bf16
__device__ __nv_bfloat16 g_Wc_h[104 * 116];
__device__ __nv_bfloat16 g_Wc_l[104 * 116];
__device__ __nv_bfloat16 g_Wde_h[104 * 116];
__device__ __nv_bfloat16 g_Wde_l[104 * 116];

// ---------------------------------------------------------------------------
__device__ __forceinline__ void mma_bf16(float* d, unsigned a0, unsigned a1,
                                         unsigned a2, unsigned a3,
                                         unsigned b0, unsigned b1) {
    asm volatile(
        "mma.sync.aligned.m16n8k16.row.col.f32.bf16.bf16.f32 "
        "{%0,%1,%2,%3},{%4,%5,%6,%7},{%8,%9},{%0,%1,%2,%3};"
        : "+f"(d[0]), "+f"(d[1]), "+f"(d[2]), "+f"(d[3])
        : "r"(a0), "r"(a1), "r"(a2), "r"(a3), "r"(b0), "r"(b1));
}

__device__ __forceinline__ void split_pack(float x, float y, unsigned& hi,
                                           unsigned& lo) {
    __nv_bfloat16 hx = __float2bfloat16(x), hy = __float2bfloat16(y);
    float lx = x - __bfloat162float(hx);
    float ly = y - __bfloat162float(hy);
    __nv_bfloat162 Hp = __halves2bfloat162(hx, hy);
    __nv_bfloat162 Lp = __halves2bfloat162(__float2bfloat16(lx),
                                           __float2bfloat16(ly));
    hi = *reinterpret_cast<unsigned*>(&Hp);
    lo = *reinterpret_cast<unsigned*>(&Lp);
}

// ---------------------------------------------------------------------------
__global__ void k_prep_wc(const float* __restrict__ W_de,
                          const float* __restrict__ W_eij) {
    int idx = blockIdx.x * blockDim.x + threadIdx.x;
    if (idx >= H * H) return;
    int k = idx / H, c = idx % H;
    float acc = 0.f;
#pragma unroll 4
    for (int m = 0; m < H; m++) acc += W_de[k * H + m] * W_eij[m * H + c];
    g_Wc[idx] = acc;
}

__global__ void k_prep_small(const float* __restrict__ W_edge,
                             const float* __restrict__ W_eij,
                             const float* __restrict__ b_edge,
                             const float* __restrict__ b_eij,
                             const float* __restrict__ b_de) {
    int idx = blockIdx.x * blockDim.x + threadIdx.x;
    if (idx < 1700) {
        int c = idx / 17, k = idx % 17;
        float v = 0.f;
        if (k < 16) {
#pragma unroll 4
            for (int m = 0; m < H; m++) v += W_edge[k * H + m] * W_eij[m * H + c];
        }
        g_Wz[idx] = v;
    } else if (idx < 3400) {
        int j = idx - 1700;
        int c = j / 17, k = j % 17;
        g_We[j] = (k < 16) ? W_edge[k * H + c] : 0.f;
    } else if (idx < 3500) {
        int c = idx - 3400;
        float v = b_eij[c];
#pragma unroll 4
        for (int m = 0; m < H; m++) v += b_edge[m] * W_eij[m * H + c];
        g_bz0[c] = v;
    } else if (idx < 3600) {
        int c = idx - 3500;
        float v = 0.f;
#pragma unroll 4
        for (int m = 0; m < H; m++) v += b_de[m] * W_eij[m * H + c];
        g_bde[c] = v;
    }
}

__global__ void k_split_wc() {
    int idx = blockIdx.x * blockDim.x + threadIdx.x;
    if (idx >= 104 * 116) return;
    int n = idx / 116, k = idx % 116;
    float v = (k < H && n < H) ? g_Wc[k * H + n] : 0.f;
    __nv_bfloat16 h = __float2bfloat16(v);
    g_Wc_h[idx] = h;
    g_Wc_l[idx] = __float2bfloat16(v - __bfloat162float(h));
}

__global__ void k_split_wde(const float* __restrict__ W_de) {
    int idx = blockIdx.x * blockDim.x + threadIdx.x;
    if (idx >= 104 * 116) return;
    int n = idx / 116, k = idx % 116;
    float v = (k < H && n < H) ? W_de[k * H + n] : 0.f;
    __nv_bfloat16 h = __float2bfloat16(v);
    g_Wde_h[idx] = h;
    g_Wde_l[idx] = __float2bfloat16(v - __bfloat162float(h));
}

__global__ void k_rowsum_ea(const float* __restrict__ ea) {
    __shared__ float sp[256];
    int i = blockIdx.x;
    int tid = threadIdx.x;
    int k = tid & 15, jg = tid >> 4;
    float part = 0.f;
    for (int j = jg; j < NATOMS; j += 16)
        part += ea[((size_t)i * NATOMS + j) * IN_EDGE + k];
    sp[tid] = part;
    __syncthreads();
    if (tid < 16) {
        float sum = 0.f;
#pragma unroll
        for (int q = 0; q < 16; q++) sum += sp[q * 16 + tid];
        g_SEa[i * IN_EDGE + tid] = sum;
    }
}

__global__ void k_init_h(const float* __restrict__ nf, const float* __restrict__ W,
                         const float* __restrict__ b, float* __restrict__ h) {
    int idx = blockIdx.x * blockDim.x + threadIdx.x;
    if (idx >= NATOMS * H) return;
    int n = idx / H, c = idx % H;
    float acc = b[c];
#pragma unroll
    for (int k = 0; k < IN_NODE; k++) acc += nf[n * IN_NODE + k] * W[k * H + c];
    h[idx] = acc;
}

// f_i/f_j with h rows staged in smem, coalesced W
__global__ void k_fij(const float* __restrict__ h, const float* __restrict__ Wi,
                      const float* __restrict__ Wj) {
    __shared__ float sh[4 * H];
    int b = blockIdx.x;                 // 192 blocks x 4 rows
    int tid = threadIdx.x;              // 256
    for (int q = tid; q < 4 * H; q += 256) sh[q] = h[b * 4 * H + q];
    __syncthreads();
    for (int o = tid; o < 800; o += 256) {
        int which = o >= 400;
        int oo = o - which * 400;
        int r = oo / H, c = oo % H;
        const float* W = which ? Wj : Wi;
        float acc = 0.f;
#pragma unroll 4
        for (int k = 0; k < H; k++) acc += sh[r * H + k] * __ldg(W + k * H + c);
        (which ? g_fj : g_fi)[(b * 4 + r) * H + c] = acc;
    }
}

__global__ void k_dots() {
    __shared__ float sA[32][17];
    __shared__ float sB[32][17];
    int tx = threadIdx.x, ty = threadIdx.y;
    int i0 = blockIdx.y * 32 + ty * 2;
    int j0 = blockIdx.x * 32 + tx * 2;
    float a00 = 0.f, a01 = 0.f, a10 = 0.f, a11 = 0.f;
    int tid = ty * 16 + tx;
    for (int k0 = 0; k0 < H; k0 += 16) {
        for (int q = tid; q < 32 * 16; q += 256) {
            int r = q >> 4, kk = q & 15;
            int ka = k0 + kk;
            sA[r][kk] = (ka < H) ? g_fi[(blockIdx.y * 32 + r) * H + ka] : 0.f;
            sB[r][kk] = (ka < H) ? g_fj[(blockIdx.x * 32 + r) * H + ka] : 0.f;
        }
        __syncthreads();
#pragma unroll
        for (int kk = 0; kk < 16; kk++) {
            float x0 = sA[ty * 2][kk], x1 = sA[ty * 2 + 1][kk];
            float y0 = sB[tx * 2][kk], y1 = sB[tx * 2 + 1][kk];
            a00 += x0 * y0; a01 += x0 * y1;
            a10 += x1 * y0; a11 += x1 * y1;
        }
        __syncthreads();
    }
    g_dots[i0 * NATOMS + j0] = a00;
    g_dots[i0 * NATOMS + j0 + 1] = a01;
    g_dots[(i0 + 1) * NATOMS + j0] = a10;
    g_dots[(i0 + 1) * NATOMS + j0 + 1] = a11;
}

// ---------------------------------------------------------------------------
// Persistent fused edge kernel. mode = 1,2,3 (iteration number).
//  mode1: f1 = relu(ea@Wz + bz0 + dots); Fsum := f1           (no MMA)
//  mode2: f2 = relu(ea@Wz + bz0 + bde + Fsum@Wc + dots); Fsum += f2   (1 GEMM)
//  mode3: f3 = relu(ea@Wz + bz0 + 2*bde + Fsum@Wc + dots);
//         e  = ea@We + b_edge + (Fsum+f3)@W_de + 3*b_de       (2 GEMMs)
// Fsum lives in the e-region of d_out; mode3 overwrites it with e.
// Modes 2/3 prefetch the next tile's Fsum into registers to hide DRAM latency.
extern __shared__ unsigned usmem[];

__global__ __launch_bounds__(ETHREADS) void k_edge(
    float* __restrict__ efs, const float* __restrict__ ea,
    const float* __restrict__ b_de_, const float* __restrict__ b_edge_,
    int mode) {
    unsigned* sWc = usmem + OFF_WC;
    unsigned* sWd = usmem + OFF_WD;
    unsigned* sFh = usmem + OFF_FH;
    unsigned* sFl = usmem + OFF_FL;
    float* sRed = (float*)(usmem + OFF_RED);
    float* sWz = (float*)(usmem + OFF_WZ);
    float* sWe = (float*)(usmem + OFF_WE2);
    float* sbz = (float*)(usmem + OFF_BZ);
    float* sbd = (float*)(usmem + OFF_BDE);
    float* sbe = (float*)(usmem + OFF_BE);

    const int tid = threadIdx.x;
    const int w = tid >> 5;
    const int lane = tid & 31;
    const int g = lane >> 2;
    const int tig = lane & 3;
    const int rw = w & 7;
    const int nh = w >> 3;
    const int n0 = nh * 7;
    const int nc = 7 - nh;
    const int rA = rw * 16 + g;
    const float bf = (float)(mode - 1);

    // ---- stage weights once ----
    for (int idx = tid; idx < 104 * RS; idx += ETHREADS) {
        sWc[idx]        = ((const unsigned*)g_Wc_h)[idx];
        sWc[6032 + idx] = ((const unsigned*)g_Wc_l)[idx];
        sWd[idx]        = ((const unsigned*)g_Wde_h)[idx];
        sWd[6032 + idx] = ((const unsigned*)g_Wde_l)[idx];
    }
    for (int idx = tid; idx < 1700; idx += ETHREADS) {
        sWz[idx] = g_Wz[idx];
        sWe[idx] = g_We[idx];
    }
    if (tid < H) {
        sbz[tid] = g_bz0[tid];
        sbd[tid] = g_bde[tid];
        sbe[tid] = b_edge_[tid];
    }
    __syncthreads();

    float2 pre[15];
#define LOADT(tt) do {                                                        \
        size_t b_ = (size_t)(tt) * BM * H;                                    \
        _Pragma("unroll")                                                     \
        for (int q_ = 0; q_ < 15; q_++) {                                     \
            int idx_ = tid + q_ * ETHREADS;                                   \
            if (idx_ < BM * RS) {                                             \
                int r_ = idx_ / RS, wd_ = idx_ - r_ * RS;                     \
                pre[q_] = (wd_ * 2 < H)                                       \
                    ? *(const float2*)(efs + b_ + r_ * H + wd_ * 2)           \
                    : make_float2(0.f, 0.f);                                  \
            }                                                                 \
        }                                                                     \
    } while (0)

    if (mode >= 2 && blockIdx.x < NTILES) LOADT(blockIdx.x);

    for (int t = blockIdx.x; t < NTILES; t += gridDim.x) {
        const int i = t / SEGS;
        const int s = t % SEGS;
        const size_t base = (size_t)t * BM * H;
        const int tnext = t + gridDim.x;

        // ---- split prefetched Fsum tile -> sF (modes 2,3) ----
        if (mode >= 2) {
#pragma unroll
            for (int q = 0; q < 15; q++) {
                int idx = tid + q * ETHREADS;
                if (idx < BM * RS) {
                    unsigned hi, lo;
                    split_pack(pre[q].x, pre[q].y, hi, lo);
                    sFh[idx] = hi;
                    sFl[idx] = lo;
                }
            }
        }
        __syncthreads();

        // mode2: prefetch next tile now (hidden behind MMA below)
        if (mode == 2 && tnext < NTILES) LOADT(tnext);

        // ---- MMA: acc = Fsum @ Wc (3-term) ----
        float acc[7][4];
#pragma unroll
        for (int n = 0; n < 7; n++)
#pragma unroll
            for (int q = 0; q < 4; q++) acc[n][q] = 0.f;

        if (mode >= 2) {
#pragma unroll
            for (int kc = 0; kc < KC; kc++) {
                int ab = rA * RS + kc * 8 + tig;
                unsigned ah0 = sFh[ab],     ah1 = sFh[ab + 8 * RS];
                unsigned ah2 = sFh[ab + 4], ah3 = sFh[ab + 8 * RS + 4];
                unsigned al0 = sFl[ab],     al1 = sFl[ab + 8 * RS];
                unsigned al2 = sFl[ab + 4], al3 = sFl[ab + 8 * RS + 4];
#pragma unroll
                for (int nn = 0; nn < 7; nn++) {
                    if (nn >= nc) break;
                    int bb = ((n0 + nn) * 8 + g) * RS + kc * 8 + tig;
                    unsigned bh0 = sWc[bb], bh1 = sWc[bb + 4];
                    unsigned bl0 = sWc[6032 + bb], bl1 = sWc[6032 + bb + 4];
                    mma_bf16(acc[nn], ah0, ah1, ah2, ah3, bh0, bh1);
                    mma_bf16(acc[nn], ah0, ah1, ah2, ah3, bl0, bl1);
                    mma_bf16(acc[nn], al0, al1, al2, al3, bh0, bh1);
                }
            }
        }

        // ---- load ea rows for z-compute ----
        float a0[16], a1[16];
        {
            const float4* p0 = (const float4*)(ea + ((size_t)t * BM + rA) * IN_EDGE);
            const float4* p1 = (const float4*)(ea + ((size_t)t * BM + rA + 8) * IN_EDGE);
#pragma unroll
            for (int q = 0; q < 4; q++) {
                float4 v = p0[q];
                a0[q * 4] = v.x; a0[q * 4 + 1] = v.y; a0[q * 4 + 2] = v.z; a0[q * 4 + 3] = v.w;
                v = p1[q];
                a1[q * 4] = v.x; a1[q * 4 + 1] = v.y; a1[q * 4 + 2] = v.z; a1[q * 4 + 3] = v.w;
            }
        }
        const float d0 = g_dots[i * NATOMS + s * BM + rA];
        const float d1 = g_dots[i * NATOMS + s * BM + rA + 8];

        // ---- f = relu(acc + z + bias + dots); rowsums; Fsum/e handling ----
        float fs[7][4];
#pragma unroll
        for (int nn = 0; nn < 7; nn++) {
            if (nn >= nc) break;
            const int n = n0 + nn;
            const int c0 = n * 8 + tig * 2;
            float f00 = 0.f, f01 = 0.f, f10 = 0.f, f11 = 0.f;
            if (c0 < H) {
                float z00 = 0.f, z01 = 0.f, z10 = 0.f, z11 = 0.f;
#pragma unroll
                for (int k = 0; k < 16; k++) {
                    float w0 = sWz[c0 * 17 + k];
                    float w1 = sWz[(c0 + 1) * 17 + k];
                    z00 += a0[k] * w0; z01 += a0[k] * w1;
                    z10 += a1[k] * w0; z11 += a1[k] * w1;
                }
                float bias0 = sbz[c0] + bf * sbd[c0];
                float bias1 = sbz[c0 + 1] + bf * sbd[c0 + 1];
                f00 = fmaxf(acc[nn][0] + z00 + bias0 + d0, 0.f);
                f01 = fmaxf(acc[nn][1] + z01 + bias1 + d0, 0.f);
                f10 = fmaxf(acc[nn][2] + z10 + bias0 + d1, 0.f);
                f11 = fmaxf(acc[nn][3] + z11 + bias1 + d1, 0.f);
            }
            float p0 = f00 + f10, p1 = f01 + f11;
            p0 += __shfl_down_sync(0xffffffffu, p0, 16);
            p0 += __shfl_down_sync(0xffffffffu, p0, 8);
            p0 += __shfl_down_sync(0xffffffffu, p0, 4);
            p1 += __shfl_down_sync(0xffffffffu, p1, 16);
            p1 += __shfl_down_sync(0xffffffffu, p1, 8);
            p1 += __shfl_down_sync(0xffffffffu, p1, 4);
            if (lane < 4 && c0 < H) {
                sRed[rw * 104 + c0] = p0;
                sRed[rw * 104 + c0 + 1] = p1;
            }
            if (c0 < H) {
                const int wi = rA * RS + n * 4 + tig;
                float o00 = 0.f, o01 = 0.f, o10 = 0.f, o11 = 0.f;
                if (mode >= 2) {
                    __nv_bfloat162 H0 = *reinterpret_cast<__nv_bfloat162*>(&sFh[wi]);
                    __nv_bfloat162 L0 = *reinterpret_cast<__nv_bfloat162*>(&sFl[wi]);
                    __nv_bfloat162 H1 = *reinterpret_cast<__nv_bfloat162*>(&sFh[wi + 8 * RS]);
                    __nv_bfloat162 L1 = *reinterpret_cast<__nv_bfloat162*>(&sFl[wi + 8 * RS]);
                    o00 = __low2float(H0) + __low2float(L0);
                    o01 = __high2float(H0) + __high2float(L0);
                    o10 = __low2float(H1) + __low2float(L1);
                    o11 = __high2float(H1) + __high2float(L1);
                }
                if (mode <= 2) {
                    *(float2*)(efs + base + rA * H + c0) = make_float2(o00 + f00, o01 + f01);
                    *(float2*)(efs + base + (rA + 8) * H + c0) = make_float2(o10 + f10, o11 + f11);
                } else {
                    fs[nn][0] = o00 + f00; fs[nn][1] = o01 + f01;
                    fs[nn][2] = o10 + f10; fs[nn][3] = o11 + f11;
                }
            }
        }

        if (mode <= 2) {
            __syncthreads();
            if (tid < H) {
                float sum = 0.f;
#pragma unroll
                for (int q = 0; q < 8; q++) sum += sRed[q * 104 + tid];
                g_PS[(s * NATOMS + i) * H + tid] = sum;
            }
            __syncthreads();
            continue;
        }

        // ---- mode3: Fsum3 -> sF, then MMA2 = Fsum3 @ W_de ----
        __syncthreads();
        if (tid < H) {
            float sum = 0.f;
#pragma unroll
            for (int q = 0; q < 8; q++) sum += sRed[q * 104 + tid];
            g_PS[(s * NATOMS + i) * H + tid] = sum;
        }
#pragma unroll
        for (int nn = 0; nn < 7; nn++) {
            if (nn >= nc) break;
            const int n = n0 + nn;
            const int c0 = n * 8 + tig * 2;
            if (c0 < H) {
                const int wi = rA * RS + n * 4 + tig;
                unsigned hi, lo;
                split_pack(fs[nn][0], fs[nn][1], hi, lo);
                sFh[wi] = hi; sFl[wi] = lo;
                split_pack(fs[nn][2], fs[nn][3], hi, lo);
                sFh[wi + 8 * RS] = hi; sFl[wi + 8 * RS] = lo;
            }
        }
        __syncthreads();

        // mode3: prefetch next tile now (fs dead; hidden behind MMA2)
        if (tnext < NTILES) LOADT(tnext);

#pragma unroll
        for (int n = 0; n < 7; n++)
#pragma unroll
            for (int q = 0; q < 4; q++) acc[n][q] = 0.f;
#pragma unroll
        for (int kc = 0; kc < KC; kc++) {
            int ab = rA * RS + kc * 8 + tig;
            unsigned ah0 = sFh[ab],     ah1 = sFh[ab + 8 * RS];
            unsigned ah2 = sFh[ab + 4], ah3 = sFh[ab + 8 * RS + 4];
            unsigned al0 = sFl[ab],     al1 = sFl[ab + 8 * RS];
            unsigned al2 = sFl[ab + 4], al3 = sFl[ab + 8 * RS + 4];
#pragma unroll
            for (int nn = 0; nn < 7; nn++) {
                if (nn >= nc) break;
                int bb = ((n0 + nn) * 8 + g) * RS + kc * 8 + tig;
                unsigned bh0 = sWd[bb], bh1 = sWd[bb + 4];
                unsigned bl0 = sWd[6032 + bb], bl1 = sWd[6032 + bb + 4];
                mma_bf16(acc[nn], ah0, ah1, ah2, ah3, bh0, bh1);
                mma_bf16(acc[nn], ah0, ah1, ah2, ah3, bl0, bl1);
                mma_bf16(acc[nn], al0, al1, al2, al3, bh0, bh1);
            }
        }

        // ---- e = ea@We + b_edge + acc + 3*b_de ----
#pragma unroll
        for (int nn = 0; nn < 7; nn++) {
            if (nn >= nc) break;
            const int n = n0 + nn;
            const int c0 = n * 8 + tig * 2;
            if (c0 < H) {
                float z00 = 0.f, z01 = 0.f, z10 = 0.f, z11 = 0.f;
#pragma unroll
                for (int k = 0; k < 16; k++) {
                    float w0 = sWe[c0 * 17 + k];
                    float w1 = sWe[(c0 + 1) * 17 + k];
                    z00 += a0[k] * w0; z01 += a0[k] * w1;
                    z10 += a1[k] * w0; z11 += a1[k] * w1;
                }
                float bias0 = sbe[c0] + 3.f * __ldg(b_de_ + c0);
                float bias1 = sbe[c0 + 1] + 3.f * __ldg(b_de_ + c0 + 1);
                *(float2*)(efs + base + rA * H + c0) =
                    make_float2(z00 + bias0 + acc[nn][0], z01 + bias1 + acc[nn][1]);
                *(float2*)(efs + base + (rA + 8) * H + c0) =
                    make_float2(z10 + bias0 + acc[nn][2], z11 + bias1 + acc[nn][3]);
            }
        }
        __syncthreads();
    }
#undef LOADT
}

// ---------------------------------------------------------------------------
// Fused node epilogue: FSrow accumulate -> S -> dV -> h update (row-local).
__global__ __launch_bounds__(128) void k_node(
    const float* __restrict__ We_, const float* __restrict__ be_,
    const float* __restrict__ Wd_, const float* __restrict__ bd_,
    const float* __restrict__ W1, const float* __restrict__ b1,
    const float* __restrict__ W2, const float* __restrict__ b2,
    float* __restrict__ h, int t, int first) {
    __shared__ float sF[H], sS[H], sV[H];
    const int i = blockIdx.x;
    const int tid = threadIdx.x;
    if (tid < H) {
        float acc = 0.f;
#pragma unroll
        for (int seg = 0; seg < SEGS; seg++)
            acc += g_PS[seg * NATOMS * H + i * H + tid];
        if (!first) acc += g_FSrow[i * H + tid];
        g_FSrow[i * H + tid] = acc;
        sF[tid] = acc;
    }
    __syncthreads();
    if (tid < H) {
        float acc = (float)NATOMS * (__ldg(be_ + tid) + (float)t * __ldg(bd_ + tid));
#pragma unroll
        for (int k = 0; k < IN_EDGE; k++)
            acc += g_SEa[i * IN_EDGE + k] * __ldg(We_ + k * H + tid);
#pragma unroll 4
        for (int k = 0; k < H; k++) acc += sF[k] * __ldg(Wd_ + k * H + tid);
        sS[tid] = acc;
    }
    __syncthreads();
    if (tid < H) {
        float acc = (float)NATOMS * __ldg(b1 + tid);
#pragma unroll 4
        for (int k = 0; k < H; k++) acc += sS[k] * __ldg(W1 + k * H + tid);
        sV[tid] = acc;
    }
    __syncthreads();
    if (tid < H) {
        float acc = __ldg(b2 + tid);
#pragma unroll 4
        for (int k = 0; k < H; k++) acc += sV[k] * __ldg(W2 + k * H + tid);
        h[i * H + tid] += acc;
    }
}

// ---------------------------------------------------------------------------
extern "C" void kernel_launch(void* const* d_in, const int* in_sizes, int n_in,
                              void* d_out, int out_size) {
    const float* node_feats = (const float*)d_in[0];
    const float* edge_attr  = (const float*)d_in[1];
    const float* W_node = (const float*)d_in[2];
    const float* b_node = (const float*)d_in[3];
    const float* W_edge = (const float*)d_in[4];
    const float* b_edge = (const float*)d_in[5];
    const float* W_eij  = (const float*)d_in[6];
    const float* b_eij  = (const float*)d_in[7];
    const float* W_i    = (const float*)d_in[8];
    const float* W_j    = (const float*)d_in[9];
    const float* W_de   = (const float*)d_in[10];
    const float* b_de   = (const float*)d_in[11];
    const float* W_dv1  = (const float*)d_in[12];
    const float* b_dv1  = (const float*)d_in[13];
    const float* W_dv2  = (const float*)d_in[14];
    const float* b_dv2  = (const float*)d_in[15];

    float* h = (float*)d_out;            // (768, 100)
    float* e = h + NATOMS * H;           // Fsum during iters 1-2, final e after iter 3

    const int smem_bytes = SMEM_WORDS * 4;
    cudaFuncSetAttribute(k_edge, cudaFuncAttributeMaxDynamicSharedMemorySize,
                         smem_bytes);

    int dev = 0, nsm = 148;
    cudaGetDevice(&dev);
    cudaDeviceGetAttribute(&nsm, cudaDevAttrMultiProcessorCount, dev);

    const int NH = NATOMS * H;

    // one-time prep
    k_prep_wc<<<(H * H + 255) / 256, 256>>>(W_de, W_eij);
    k_prep_small<<<(3600 + 255) / 256, 256>>>(W_edge, W_eij, b_edge, b_eij, b_de);
    k_split_wc<<<(104 * 116 + 255) / 256, 256>>>();
    k_split_wde<<<(104 * 116 + 255) / 256, 256>>>(W_de);
    k_rowsum_ea<<<NATOMS, 256>>>(edge_attr);
    k_init_h<<<(NH + 255) / 256, 256>>>(node_feats, W_node, b_node, h);

    for (int it = 0; it < ITERS; it++) {
        k_fij<<<192, 256>>>(h, W_i, W_j);
        k_dots<<<dim3(24, 24), dim3(16, 16)>>>();
        k_edge<<<nsm, ETHREADS, smem_bytes>>>(e, edge_attr, b_de, b_edge, it + 1);
        k_node<<<NATOMS, 128>>>(W_edge, b_edge, W_de, b_de, W_dv1, b_dv1,
                                W_dv2, b_dv2, h, it + 1, it == 0 ? 1 : 0);
    }
}

// round 13
// speedup vs baseline: 1.0277x; 1.0277x over previous
#include <cuda_runtime.h>
#include <cuda_bf16.h>

#define NATOMS 768
#define H 100
#define IN_NODE 32
#define IN_EDGE 16
#define ITERS 3
#define NE (NATOMS * NATOMS)       // 589824

#define BM 128
#define NTILES (NE / BM)            // 4608
#define SEGS 6
#define KC 7                        // k16 steps covering 0..111
#define RS 58                       // row stride in u32 words (116 bf16)
#define ETHREADS 512

// smem word offsets for k_edge
#define OFF_WC 0                    // Wc hi/lo: 2 * 6032
#define OFF_WD 12064                // Wde hi/lo: 2 * 6032
#define OFF_FH 24128                // Fsum hi: 7424
#define OFF_FL 31552                // Fsum lo: 7424
#define OFF_RED 38976               // 8*104 f32
#define OFF_WZ 39808                // 1700 f32
#define OFF_WE2 41508               // 1700 f32
#define OFF_BZ 43208                // 100
#define OFF_BDE 43308               // 100
#define OFF_BE 43408                // 100
#define SMEM_WORDS 43508            // 174 KB

// ---- scratch (device globals; no allocation allowed) ----
__device__ float g_dots[NE];
__device__ float g_fi[NATOMS * H];
__device__ float g_fj[NATOMS * H];
__device__ float g_PS[SEGS * NATOMS * H];
__device__ float g_FSrow[NATOMS * H];
__device__ float g_SEa[NATOMS * IN_EDGE];
__device__ float g_Wc[H * H];              // W_de @ W_eij (fp32)
__device__ float g_Wz[H * 17];             // (W_edge@W_eij)^T padded: [c*17+k]
__device__ float g_We[H * 17];             // W_edge^T padded: [c*17+k]
__device__ float g_bz0[H];                 // b_edge@W_eij + b_eij
__device__ float g_bde[H];                 // b_de@W_eij
// 3-term split weights, n-major 104 x 116 bf16
__device__ __nv_bfloat16 g_Wc_h[104 * 116];
__device__ __nv_bfloat16 g_Wc_l[104 * 116];
__device__ __nv_bfloat16 g_Wde_h[104 * 116];
__device__ __nv_bfloat16 g_Wde_l[104 * 116];

// ---------------------------------------------------------------------------
__device__ __forceinline__ void mma_bf16(float* d, unsigned a0, unsigned a1,
                                         unsigned a2, unsigned a3,
                                         unsigned b0, unsigned b1) {
    asm volatile(
        "mma.sync.aligned.m16n8k16.row.col.f32.bf16.bf16.f32 "
        "{%0,%1,%2,%3},{%4,%5,%6,%7},{%8,%9},{%0,%1,%2,%3};"
        : "+f"(d[0]), "+f"(d[1]), "+f"(d[2]), "+f"(d[3])
        : "r"(a0), "r"(a1), "r"(a2), "r"(a3), "r"(b0), "r"(b1));
}

__device__ __forceinline__ void split_pack(float x, float y, unsigned& hi,
                                           unsigned& lo) {
    __nv_bfloat16 hx = __float2bfloat16(x), hy = __float2bfloat16(y);
    float lx = x - __bfloat162float(hx);
    float ly = y - __bfloat162float(hy);
    __nv_bfloat162 Hp = __halves2bfloat162(hx, hy);
    __nv_bfloat162 Lp = __halves2bfloat162(__float2bfloat16(lx),
                                           __float2bfloat16(ly));
    hi = *reinterpret_cast<unsigned*>(&Hp);
    lo = *reinterpret_cast<unsigned*>(&Lp);
}

// ---------------------------------------------------------------------------
__global__ void k_prep_wc(const float* __restrict__ W_de,
                          const float* __restrict__ W_eij) {
    int idx = blockIdx.x * blockDim.x + threadIdx.x;
    if (idx >= H * H) return;
    int k = idx / H, c = idx % H;
    float acc = 0.f;
#pragma unroll 4
    for (int m = 0; m < H; m++) acc += W_de[k * H + m] * W_eij[m * H + c];
    g_Wc[idx] = acc;
}

__global__ void k_prep_small(const float* __restrict__ W_edge,
                             const float* __restrict__ W_eij,
                             const float* __restrict__ b_edge,
                             const float* __restrict__ b_eij,
                             const float* __restrict__ b_de) {
    int idx = blockIdx.x * blockDim.x + threadIdx.x;
    if (idx < 1700) {
        int c = idx / 17, k = idx % 17;
        float v = 0.f;
        if (k < 16) {
#pragma unroll 4
            for (int m = 0; m < H; m++) v += W_edge[k * H + m] * W_eij[m * H + c];
        }
        g_Wz[idx] = v;
    } else if (idx < 3400) {
        int j = idx - 1700;
        int c = j / 17, k = j % 17;
        g_We[j] = (k < 16) ? W_edge[k * H + c] : 0.f;
    } else if (idx < 3500) {
        int c = idx - 3400;
        float v = b_eij[c];
#pragma unroll 4
        for (int m = 0; m < H; m++) v += b_edge[m] * W_eij[m * H + c];
        g_bz0[c] = v;
    } else if (idx < 3600) {
        int c = idx - 3500;
        float v = 0.f;
#pragma unroll 4
        for (int m = 0; m < H; m++) v += b_de[m] * W_eij[m * H + c];
        g_bde[c] = v;
    }
}

__global__ void k_split_wc() {
    int idx = blockIdx.x * blockDim.x + threadIdx.x;
    if (idx >= 104 * 116) return;
    int n = idx / 116, k = idx % 116;
    float v = (k < H && n < H) ? g_Wc[k * H + n] : 0.f;
    __nv_bfloat16 h = __float2bfloat16(v);
    g_Wc_h[idx] = h;
    g_Wc_l[idx] = __float2bfloat16(v - __bfloat162float(h));
}

__global__ void k_split_wde(const float* __restrict__ W_de) {
    int idx = blockIdx.x * blockDim.x + threadIdx.x;
    if (idx >= 104 * 116) return;
    int n = idx / 116, k = idx % 116;
    float v = (k < H && n < H) ? W_de[k * H + n] : 0.f;
    __nv_bfloat16 h = __float2bfloat16(v);
    g_Wde_h[idx] = h;
    g_Wde_l[idx] = __float2bfloat16(v - __bfloat162float(h));
}

__global__ void k_rowsum_ea(const float* __restrict__ ea) {
    __shared__ float sp[256];
    int i = blockIdx.x;
    int tid = threadIdx.x;
    int k = tid & 15, jg = tid >> 4;
    float part = 0.f;
    for (int j = jg; j < NATOMS; j += 16)
        part += ea[((size_t)i * NATOMS + j) * IN_EDGE + k];
    sp[tid] = part;
    __syncthreads();
    if (tid < 16) {
        float sum = 0.f;
#pragma unroll
        for (int q = 0; q < 16; q++) sum += sp[q * 16 + tid];
        g_SEa[i * IN_EDGE + tid] = sum;
    }
}

__global__ void k_init_h(const float* __restrict__ nf, const float* __restrict__ W,
                         const float* __restrict__ b, float* __restrict__ h) {
    int idx = blockIdx.x * blockDim.x + threadIdx.x;
    if (idx >= NATOMS * H) return;
    int n = idx / H, c = idx % H;
    float acc = b[c];
#pragma unroll
    for (int k = 0; k < IN_NODE; k++) acc += nf[n * IN_NODE + k] * W[k * H + c];
    h[idx] = acc;
}

// f_i/f_j with h rows staged in smem, coalesced W
__global__ void k_fij(const float* __restrict__ h, const float* __restrict__ Wi,
                      const float* __restrict__ Wj) {
    __shared__ float sh[4 * H];
    int b = blockIdx.x;                 // 192 blocks x 4 rows
    int tid = threadIdx.x;              // 256
    for (int q = tid; q < 4 * H; q += 256) sh[q] = h[b * 4 * H + q];
    __syncthreads();
    for (int o = tid; o < 800; o += 256) {
        int which = o >= 400;
        int oo = o - which * 400;
        int r = oo / H, c = oo % H;
        const float* W = which ? Wj : Wi;
        float acc = 0.f;
#pragma unroll 4
        for (int k = 0; k < H; k++) acc += sh[r * H + k] * __ldg(W + k * H + c);
        (which ? g_fj : g_fi)[(b * 4 + r) * H + c] = acc;
    }
}

__global__ void k_dots() {
    __shared__ float sA[32][17];
    __shared__ float sB[32][17];
    int tx = threadIdx.x, ty = threadIdx.y;
    int i0 = blockIdx.y * 32 + ty * 2;
    int j0 = blockIdx.x * 32 + tx * 2;
    float a00 = 0.f, a01 = 0.f, a10 = 0.f, a11 = 0.f;
    int tid = ty * 16 + tx;
    for (int k0 = 0; k0 < H; k0 += 16) {
        for (int q = tid; q < 32 * 16; q += 256) {
            int r = q >> 4, kk = q & 15;
            int ka = k0 + kk;
            sA[r][kk] = (ka < H) ? g_fi[(blockIdx.y * 32 + r) * H + ka] : 0.f;
            sB[r][kk] = (ka < H) ? g_fj[(blockIdx.x * 32 + r) * H + ka] : 0.f;
        }
        __syncthreads();
#pragma unroll
        for (int kk = 0; kk < 16; kk++) {
            float x0 = sA[ty * 2][kk], x1 = sA[ty * 2 + 1][kk];
            float y0 = sB[tx * 2][kk], y1 = sB[tx * 2 + 1][kk];
            a00 += x0 * y0; a01 += x0 * y1;
            a10 += x1 * y0; a11 += x1 * y1;
        }
        __syncthreads();
    }
    g_dots[i0 * NATOMS + j0] = a00;
    g_dots[i0 * NATOMS + j0 + 1] = a01;
    g_dots[(i0 + 1) * NATOMS + j0] = a10;
    g_dots[(i0 + 1) * NATOMS + j0 + 1] = a11;
}

// ---------------------------------------------------------------------------
// Persistent fused edge kernel (R11 staging — no register prefetch).
//  mode1: f1 = relu(ea@Wz + bz0 + dots); Fsum := f1           (no MMA)
//  mode2: f2 = relu(ea@Wz + bz0 + bde + Fsum@Wc + dots); Fsum += f2   (1 GEMM)
//  mode3: f3 = relu(ea@Wz + bz0 + 2*bde + Fsum@Wc + dots);
//         e  = ea@We + b_edge + (Fsum+f3)@W_de + 3*b_de       (2 GEMMs)
extern __shared__ unsigned usmem[];

__global__ __launch_bounds__(ETHREADS) void k_edge(
    float* __restrict__ efs, const float* __restrict__ ea,
    const float* __restrict__ b_de_, const float* __restrict__ b_edge_,
    int mode) {
    unsigned* sWc = usmem + OFF_WC;
    unsigned* sWd = usmem + OFF_WD;
    unsigned* sFh = usmem + OFF_FH;
    unsigned* sFl = usmem + OFF_FL;
    float* sRed = (float*)(usmem + OFF_RED);
    float* sWz = (float*)(usmem + OFF_WZ);
    float* sWe = (float*)(usmem + OFF_WE2);
    float* sbz = (float*)(usmem + OFF_BZ);
    float* sbd = (float*)(usmem + OFF_BDE);
    float* sbe = (float*)(usmem + OFF_BE);

    const int tid = threadIdx.x;
    const int w = tid >> 5;
    const int lane = tid & 31;
    const int g = lane >> 2;
    const int tig = lane & 3;
    const int rw = w & 7;
    const int nh = w >> 3;
    const int n0 = nh * 7;
    const int nc = 7 - nh;
    const int rA = rw * 16 + g;
    const float bf = (float)(mode - 1);

    // ---- stage weights once ----
    for (int idx = tid; idx < 104 * RS; idx += ETHREADS) {
        sWc[idx]        = ((const unsigned*)g_Wc_h)[idx];
        sWc[6032 + idx] = ((const unsigned*)g_Wc_l)[idx];
        sWd[idx]        = ((const unsigned*)g_Wde_h)[idx];
        sWd[6032 + idx] = ((const unsigned*)g_Wde_l)[idx];
    }
    for (int idx = tid; idx < 1700; idx += ETHREADS) {
        sWz[idx] = g_Wz[idx];
        sWe[idx] = g_We[idx];
    }
    if (tid < H) {
        sbz[tid] = g_bz0[tid];
        sbd[tid] = g_bde[tid];
        sbe[tid] = b_edge_[tid];
    }
    __syncthreads();

    for (int t = blockIdx.x; t < NTILES; t += gridDim.x) {
        const int i = t / SEGS;
        const int s = t % SEGS;
        const size_t base = (size_t)t * BM * H;

        // ---- stage Fsum tile (modes 2,3) ----
        if (mode >= 2) {
            for (int idx = tid; idx < BM * RS; idx += ETHREADS) {
                int r = idx / RS, wd = idx - r * RS;
                float v0 = 0.f, v1 = 0.f;
                if (wd * 2 < H) {
                    float2 p2 = *(const float2*)(efs + base + r * H + wd * 2);
                    v0 = p2.x; v1 = p2.y;
                }
                unsigned hi, lo;
                split_pack(v0, v1, hi, lo);
                sFh[idx] = hi;
                sFl[idx] = lo;
            }
        }
        __syncthreads();

        // ---- MMA: acc = Fsum @ Wc (3-term) ----
        float acc[7][4];
#pragma unroll
        for (int n = 0; n < 7; n++)
#pragma unroll
            for (int q = 0; q < 4; q++) acc[n][q] = 0.f;

        if (mode >= 2) {
#pragma unroll
            for (int kc = 0; kc < KC; kc++) {
                int ab = rA * RS + kc * 8 + tig;
                unsigned ah0 = sFh[ab],     ah1 = sFh[ab + 8 * RS];
                unsigned ah2 = sFh[ab + 4], ah3 = sFh[ab + 8 * RS + 4];
                unsigned al0 = sFl[ab],     al1 = sFl[ab + 8 * RS];
                unsigned al2 = sFl[ab + 4], al3 = sFl[ab + 8 * RS + 4];
#pragma unroll
                for (int nn = 0; nn < 7; nn++) {
                    if (nn >= nc) break;
                    int bb = ((n0 + nn) * 8 + g) * RS + kc * 8 + tig;
                    unsigned bh0 = sWc[bb], bh1 = sWc[bb + 4];
                    unsigned bl0 = sWc[6032 + bb], bl1 = sWc[6032 + bb + 4];
                    mma_bf16(acc[nn], ah0, ah1, ah2, ah3, bh0, bh1);
                    mma_bf16(acc[nn], ah0, ah1, ah2, ah3, bl0, bl1);
                    mma_bf16(acc[nn], al0, al1, al2, al3, bh0, bh1);
                }
            }
        }

        // ---- load ea rows for z-compute ----
        float a0[16], a1[16];
        {
            const float4* p0 = (const float4*)(ea + ((size_t)t * BM + rA) * IN_EDGE);
            const float4* p1 = (const float4*)(ea + ((size_t)t * BM + rA + 8) * IN_EDGE);
#pragma unroll
            for (int q = 0; q < 4; q++) {
                float4 v = p0[q];
                a0[q * 4] = v.x; a0[q * 4 + 1] = v.y; a0[q * 4 + 2] = v.z; a0[q * 4 + 3] = v.w;
                v = p1[q];
                a1[q * 4] = v.x; a1[q * 4 + 1] = v.y; a1[q * 4 + 2] = v.z; a1[q * 4 + 3] = v.w;
            }
        }
        const float d0 = g_dots[i * NATOMS + s * BM + rA];
        const float d1 = g_dots[i * NATOMS + s * BM + rA + 8];

        // ---- f = relu(acc + z + bias + dots); rowsums; Fsum/e handling ----
        float fs[7][4];
#pragma unroll
        for (int nn = 0; nn < 7; nn++) {
            if (nn >= nc) break;
            const int n = n0 + nn;
            const int c0 = n * 8 + tig * 2;
            float f00 = 0.f, f01 = 0.f, f10 = 0.f, f11 = 0.f;
            if (c0 < H) {
                float z00 = 0.f, z01 = 0.f, z10 = 0.f, z11 = 0.f;
#pragma unroll
                for (int k = 0; k < 16; k++) {
                    float w0 = sWz[c0 * 17 + k];
                    float w1 = sWz[(c0 + 1) * 17 + k];
                    z00 += a0[k] * w0; z01 += a0[k] * w1;
                    z10 += a1[k] * w0; z11 += a1[k] * w1;
                }
                float bias0 = sbz[c0] + bf * sbd[c0];
                float bias1 = sbz[c0 + 1] + bf * sbd[c0 + 1];
                f00 = fmaxf(acc[nn][0] + z00 + bias0 + d0, 0.f);
                f01 = fmaxf(acc[nn][1] + z01 + bias1 + d0, 0.f);
                f10 = fmaxf(acc[nn][2] + z10 + bias0 + d1, 0.f);
                f11 = fmaxf(acc[nn][3] + z11 + bias1 + d1, 0.f);
            }
            float p0 = f00 + f10, p1 = f01 + f11;
            p0 += __shfl_down_sync(0xffffffffu, p0, 16);
            p0 += __shfl_down_sync(0xffffffffu, p0, 8);
            p0 += __shfl_down_sync(0xffffffffu, p0, 4);
            p1 += __shfl_down_sync(0xffffffffu, p1, 16);
            p1 += __shfl_down_sync(0xffffffffu, p1, 8);
            p1 += __shfl_down_sync(0xffffffffu, p1, 4);
            if (lane < 4 && c0 < H) {
                sRed[rw * 104 + c0] = p0;
                sRed[rw * 104 + c0 + 1] = p1;
            }
            if (c0 < H) {
                const int wi = rA * RS + n * 4 + tig;
                float o00 = 0.f, o01 = 0.f, o10 = 0.f, o11 = 0.f;
                if (mode >= 2) {
                    __nv_bfloat162 H0 = *reinterpret_cast<__nv_bfloat162*>(&sFh[wi]);
                    __nv_bfloat162 L0 = *reinterpret_cast<__nv_bfloat162*>(&sFl[wi]);
                    __nv_bfloat162 H1 = *reinterpret_cast<__nv_bfloat162*>(&sFh[wi + 8 * RS]);
                    __nv_bfloat162 L1 = *reinterpret_cast<__nv_bfloat162*>(&sFl[wi + 8 * RS]);
                    o00 = __low2float(H0) + __low2float(L0);
                    o01 = __high2float(H0) + __high2float(L0);
                    o10 = __low2float(H1) + __low2float(L1);
                    o11 = __high2float(H1) + __high2float(L1);
                }
                if (mode <= 2) {
                    *(float2*)(efs + base + rA * H + c0) = make_float2(o00 + f00, o01 + f01);
                    *(float2*)(efs + base + (rA + 8) * H + c0) = make_float2(o10 + f10, o11 + f11);
                } else {
                    fs[nn][0] = o00 + f00; fs[nn][1] = o01 + f01;
                    fs[nn][2] = o10 + f10; fs[nn][3] = o11 + f11;
                }
            }
        }

        if (mode <= 2) {
            __syncthreads();
            if (tid < H) {
                float sum = 0.f;
#pragma unroll
                for (int q = 0; q < 8; q++) sum += sRed[q * 104 + tid];
                g_PS[(s * NATOMS + i) * H + tid] = sum;
            }
            __syncthreads();
            continue;
        }

        // ---- mode3: Fsum3 -> sF, then MMA2 = Fsum3 @ W_de ----
        __syncthreads();
        if (tid < H) {
            float sum = 0.f;
#pragma unroll
            for (int q = 0; q < 8; q++) sum += sRed[q * 104 + tid];
            g_PS[(s * NATOMS + i) * H + tid] = sum;
        }
#pragma unroll
        for (int nn = 0; nn < 7; nn++) {
            if (nn >= nc) break;
            const int n = n0 + nn;
            const int c0 = n * 8 + tig * 2;
            if (c0 < H) {
                const int wi = rA * RS + n * 4 + tig;
                unsigned hi, lo;
                split_pack(fs[nn][0], fs[nn][1], hi, lo);
                sFh[wi] = hi; sFl[wi] = lo;
                split_pack(fs[nn][2], fs[nn][3], hi, lo);
                sFh[wi + 8 * RS] = hi; sFl[wi + 8 * RS] = lo;
            }
        }
        __syncthreads();

#pragma unroll
        for (int n = 0; n < 7; n++)
#pragma unroll
            for (int q = 0; q < 4; q++) acc[n][q] = 0.f;
#pragma unroll
        for (int kc = 0; kc < KC; kc++) {
            int ab = rA * RS + kc * 8 + tig;
            unsigned ah0 = sFh[ab],     ah1 = sFh[ab + 8 * RS];
            unsigned ah2 = sFh[ab + 4], ah3 = sFh[ab + 8 * RS + 4];
            unsigned al0 = sFl[ab],     al1 = sFl[ab + 8 * RS];
            unsigned al2 = sFl[ab + 4], al3 = sFl[ab + 8 * RS + 4];
#pragma unroll
            for (int nn = 0; nn < 7; nn++) {
                if (nn >= nc) break;
                int bb = ((n0 + nn) * 8 + g) * RS + kc * 8 + tig;
                unsigned bh0 = sWd[bb], bh1 = sWd[bb + 4];
                unsigned bl0 = sWd[6032 + bb], bl1 = sWd[6032 + bb + 4];
                mma_bf16(acc[nn], ah0, ah1, ah2, ah3, bh0, bh1);
                mma_bf16(acc[nn], ah0, ah1, ah2, ah3, bl0, bl1);
                mma_bf16(acc[nn], al0, al1, al2, al3, bh0, bh1);
            }
        }

        // ---- e = ea@We + b_edge + acc + 3*b_de ----
#pragma unroll
        for (int nn = 0; nn < 7; nn++) {
            if (nn >= nc) break;
            const int n = n0 + nn;
            const int c0 = n * 8 + tig * 2;
            if (c0 < H) {
                float z00 = 0.f, z01 = 0.f, z10 = 0.f, z11 = 0.f;
#pragma unroll
                for (int k = 0; k < 16; k++) {
                    float w0 = sWe[c0 * 17 + k];
                    float w1 = sWe[(c0 + 1) * 17 + k];
                    z00 += a0[k] * w0; z01 += a0[k] * w1;
                    z10 += a1[k] * w0; z11 += a1[k] * w1;
                }
                float bias0 = sbe[c0] + 3.f * __ldg(b_de_ + c0);
                float bias1 = sbe[c0 + 1] + 3.f * __ldg(b_de_ + c0 + 1);
                *(float2*)(efs + base + rA * H + c0) =
                    make_float2(z00 + bias0 + acc[nn][0], z01 + bias1 + acc[nn][1]);
                *(float2*)(efs + base + (rA + 8) * H + c0) =
                    make_float2(z10 + bias0 + acc[nn][2], z11 + bias1 + acc[nn][3]);
            }
        }
        __syncthreads();
    }
}

// ---------------------------------------------------------------------------
// Fused node epilogue: FSrow accumulate -> S -> dV -> h update (row-local).
__global__ __launch_bounds__(128) void k_node(
    const float* __restrict__ We_, const float* __restrict__ be_,
    const float* __restrict__ Wd_, const float* __restrict__ bd_,
    const float* __restrict__ W1, const float* __restrict__ b1,
    const float* __restrict__ W2, const float* __restrict__ b2,
    float* __restrict__ h, int t, int first) {
    __shared__ float sF[H], sS[H], sV[H];
    const int i = blockIdx.x;
    const int tid = threadIdx.x;
    if (tid < H) {
        float acc = 0.f;
#pragma unroll
        for (int seg = 0; seg < SEGS; seg++)
            acc += g_PS[seg * NATOMS * H + i * H + tid];
        if (!first) acc += g_FSrow[i * H + tid];
        g_FSrow[i * H + tid] = acc;
        sF[tid] = acc;
    }
    __syncthreads();
    if (tid < H) {
        float acc = (float)NATOMS * (__ldg(be_ + tid) + (float)t * __ldg(bd_ + tid));
#pragma unroll
        for (int k = 0; k < IN_EDGE; k++)
            acc += g_SEa[i * IN_EDGE + k] * __ldg(We_ + k * H + tid);
#pragma unroll 4
        for (int k = 0; k < H; k++) acc += sF[k] * __ldg(Wd_ + k * H + tid);
        sS[tid] = acc;
    }
    __syncthreads();
    if (tid < H) {
        float acc = (float)NATOMS * __ldg(b1 + tid);
#pragma unroll 4
        for (int k = 0; k < H; k++) acc += sS[k] * __ldg(W1 + k * H + tid);
        sV[tid] = acc;
    }
    __syncthreads();
    if (tid < H) {
        float acc = __ldg(b2 + tid);
#pragma unroll 4
        for (int k = 0; k < H; k++) acc += sV[k] * __ldg(W2 + k * H + tid);
        h[i * H + tid] += acc;
    }
}

// ---------------------------------------------------------------------------
extern "C" void kernel_launch(void* const* d_in, const int* in_sizes, int n_in,
                              void* d_out, int out_size) {
    const float* node_feats = (const float*)d_in[0];
    const float* edge_attr  = (const float*)d_in[1];
    const float* W_node = (const float*)d_in[2];
    const float* b_node = (const float*)d_in[3];
    const float* W_edge = (const float*)d_in[4];
    const float* b_edge = (const float*)d_in[5];
    const float* W_eij  = (const float*)d_in[6];
    const float* b_eij  = (const float*)d_in[7];
    const float* W_i    = (const float*)d_in[8];
    const float* W_j    = (const float*)d_in[9];
    const float* W_de   = (const float*)d_in[10];
    const float* b_de   = (const float*)d_in[11];
    const float* W_dv1  = (const float*)d_in[12];
    const float* b_dv1  = (const float*)d_in[13];
    const float* W_dv2  = (const float*)d_in[14];
    const float* b_dv2  = (const float*)d_in[15];

    float* h = (float*)d_out;            // (768, 100)
    float* e = h + NATOMS * H;           // Fsum during iters 1-2, final e after iter 3

    const int smem_bytes = SMEM_WORDS * 4;
    cudaFuncSetAttribute(k_edge, cudaFuncAttributeMaxDynamicSharedMemorySize,
                         smem_bytes);

    int dev = 0, nsm = 148;
    cudaGetDevice(&dev);
    cudaDeviceGetAttribute(&nsm, cudaDevAttrMultiProcessorCount, dev);

    const int NH = NATOMS * H;

    // one-time prep
    k_prep_wc<<<(H * H + 255) / 256, 256>>>(W_de, W_eij);
    k_prep_small<<<(3600 + 255) / 256, 256>>>(W_edge, W_eij, b_edge, b_eij, b_de);
    k_split_wc<<<(104 * 116 + 255) / 256, 256>>>();
    k_split_wde<<<(104 * 116 + 255) / 256, 256>>>(W_de);
    k_rowsum_ea<<<NATOMS, 256>>>(edge_attr);
    k_init_h<<<(NH + 255) / 256, 256>>>(node_feats, W_node, b_node, h);

    for (int it = 0; it < ITERS; it++) {
        k_fij<<<192, 256>>>(h, W_i, W_j);
        k_dots<<<dim3(24, 24), dim3(16, 16)>>>();
        k_edge<<<nsm, ETHREADS, smem_bytes>>>(e, edge_attr, b_de, b_edge, it + 1);
        k_node<<<NATOMS, 128>>>(W_edge, b_edge, W_de, b_de, W_dv1, b_dv1,
                                W_dv2, b_dv2, h, it + 1, it == 0 ? 1 : 0);
    }
}